// round 9
// baseline (speedup 1.0000x reference)
#include <cuda_runtime.h>
#include <cuda_bf16.h>

// Problem constants (fixed by reference)
#define BB      8
#define NN      2048
#define DD      256
#define KSTEPS  10
#define OUTD    15
#define MAXN    256
#define TOTROWS (BB * NN)   // 16384

// ---- static device scratch (no allocations allowed) ----
__device__ float          g_H  [TOTROWS * DD];   // 16 MB fp32 master H
__device__ __nv_bfloat16  g_Hbf[TOTROWS * DD];   //  8 MB bf16 mirror (gather source)
__device__ float          g_AH [TOTROWS * DD];   // 16 MB A @ H result per step
__device__ short          g_col[TOTROWS * MAXN]; //  8 MB padded CSR column indices
__device__ int            g_deg[TOTROWS];
__device__ float          g_inv[TOTROWS];        // 1 / max(deg, 1)

// ---- packed f32x2 helpers (Blackwell FFMA2) ----
#define FMA2(acc, a, b) \
    asm("fma.rn.f32x2 %0, %1, %2, %0;" : "+l"(acc) : "l"(a), "l"(b))

__device__ __forceinline__ unsigned long long pack2(float x) {
    unsigned long long r;
    asm("mov.b64 %0, {%1, %1};" : "=l"(r) : "r"(__float_as_uint(x)));
    return r;
}

__device__ __forceinline__ void unpack2(unsigned long long v, float& lo, float& hi) {
    unsigned a, b;
    asm("mov.b64 {%0, %1}, %2;" : "=r"(a), "=r"(b) : "l"(v));
    lo = __uint_as_float(a);
    hi = __uint_as_float(b);
}

// =====================================================================
// Kernel 1: adjacency build. One warp per row: ballot-compact nonzero
// columns of (Yr!=0 || Yi!=0), excluding the diagonal. DRAM-bound.
// =====================================================================
__global__ void __launch_bounds__(256) adj_kernel(const float* __restrict__ Yr,
                                                  const float* __restrict__ Yi) {
    const int warp = (blockIdx.x * blockDim.x + threadIdx.x) >> 5; // global row
    const int lane = threadIdx.x & 31;
    if (warp >= TOTROWS) return;
    const int i = warp & (NN - 1);
    const float* yr = Yr + (size_t)warp * NN;
    const float* yi = Yi + (size_t)warp * NN;
    short* cols = g_col + (size_t)warp * MAXN;

    int count = 0;
    #pragma unroll 4
    for (int j0 = 0; j0 < NN; j0 += 32) {
        const int j = j0 + lane;
        const bool nz = (j != i) && ((yr[j] != 0.0f) || (yi[j] != 0.0f));
        const unsigned m = __ballot_sync(0xffffffffu, nz);
        if (nz) {
            const int pos = count + __popc(m & ((1u << lane) - 1u));
            if (pos < MAXN) cols[pos] = (short)j;
        }
        count += __popc(m);
    }
    if (lane == 0) {
        g_deg[warp] = count < MAXN ? count : MAXN;
        g_inv[warp] = 1.0f / (float)(count > 1 ? count : 1);
    }
}

// =====================================================================
// Kernel 2: role-selected embedding. One block per node, thread = d.
// Writes fp32 master and bf16 mirror.
// =====================================================================
__global__ void __launch_bounds__(256) emb_kernel(const int*   __restrict__ bus_type,
                                                  const float* __restrict__ features,
                                                  const float* __restrict__ W_emb,
                                                  const float* __restrict__ b_emb) {
    const int node = blockIdx.x;
    const int d = threadIdx.x;
    const int r = bus_type[node] - 1;          // 0..2
    const float f0 = features[node * 2 + 0];
    const float f1 = features[node * 2 + 1];
    const float w0 = W_emb[(r * 2 + 0) * DD + d];
    const float w1 = W_emb[(r * 2 + 1) * DD + d];
    const float h = tanhf(fmaf(f0, w0, fmaf(f1, w1, b_emb[r * DD + d])));
    g_H  [(size_t)node * DD + d] = h;
    g_Hbf[(size_t)node * DD + d] = __float2bfloat16(h);
}

// =====================================================================
// Kernel 3: SpMM  AH[row,:] = inv * sum_{j in nbrs(row)} Hbf[j,:]
// One warp per row (4 rows sequential). Lane owns d = lane*8..lane*8+7.
// bf16 gather, fp32 accumulate. Unroll 8 deepens L2 MLP.
// =====================================================================
__device__ __forceinline__ void accum_bf16x8(float a[8], const uint4 v) {
    float2 f;
    f = __bfloat1622float2(*reinterpret_cast<const __nv_bfloat162*>(&v.x));
    a[0] += f.x; a[1] += f.y;
    f = __bfloat1622float2(*reinterpret_cast<const __nv_bfloat162*>(&v.y));
    a[2] += f.x; a[3] += f.y;
    f = __bfloat1622float2(*reinterpret_cast<const __nv_bfloat162*>(&v.z));
    a[4] += f.x; a[5] += f.y;
    f = __bfloat1622float2(*reinterpret_cast<const __nv_bfloat162*>(&v.w));
    a[6] += f.x; a[7] += f.y;
}

__global__ void __launch_bounds__(256) spmm_kernel() {
    const int lane = threadIdx.x & 31;
    const int warp = threadIdx.x >> 5;
    const int row0 = blockIdx.x * 32 + warp * 4;

    for (int rr = 0; rr < 4; ++rr) {
        const int row = row0 + rr;
        const int b = row >> 11;
        const __nv_bfloat16* __restrict__ Hb = g_Hbf + (size_t)b * NN * DD;
        const short* __restrict__ cols = g_col + (size_t)row * MAXN;
        const int deg = g_deg[row];
        const float inv = g_inv[row];

        float a[8];
        #pragma unroll
        for (int q = 0; q < 8; ++q) a[q] = 0.0f;

        int t = 0;
        for (; t + 8 <= deg; t += 8) {
            uint4 v[8];
            #pragma unroll
            for (int u = 0; u < 8; ++u) {
                const int j = cols[t + u];
                v[u] = *((const uint4*)(Hb + (size_t)j * DD) + lane);
            }
            #pragma unroll
            for (int u = 0; u < 8; ++u) accum_bf16x8(a, v[u]);
        }
        for (; t < deg; ++t) {
            const int j0 = cols[t];
            const uint4 v0 = *((const uint4*)(Hb + (size_t)j0 * DD) + lane);
            accum_bf16x8(a, v0);
        }

        float4* outp = (float4*)(g_AH + (size_t)row * DD);
        outp[lane * 2 + 0] = make_float4(a[0] * inv, a[1] * inv, a[2] * inv, a[3] * inv);
        outp[lane * 2 + 1] = make_float4(a[4] * inv, a[5] * inv, a[6] * inv, a[7] * inv);
    }
}

// =====================================================================
// Kernel 4: dense update  H += tanh(AH @ Wl + bl)  (in-place on H:
// legal because the sparse gather already consumed H into g_AH).
// SGEMM M=16384, N=256(full), K=256 with packed fma.rn.f32x2.
// v2: CTA tile 64x256, thread tile 4m x 16n (32 acc2 = 64 regs),
// k-chunk 16, __launch_bounds__(256,2) -> 2 CTAs/SM = 16 warps to
// hide LDS/BAR latency (v1 ran 1.0 FFMA2/cyc at 8 warps; target ~1.7).
// =====================================================================
__global__ void __launch_bounds__(256, 2) update_kernel(const float* __restrict__ Wl,
                                                        const float* __restrict__ bl) {
    __shared__ float As[16][68];    // [k][m], transposed A chunk (64 rows)
    __shared__ float Bs[16][260];   // [k][n], full 256-wide Wl chunk

    const int tid   = threadIdx.x;
    const int mBase = blockIdx.x * 64;

    // global-load indices
    const int mA = tid & 63;            // 0..63
    const int hA = (tid >> 6) * 4;      // 0,4,8,12 (k offset within chunk)
    const int kB = tid >> 5;            // 0..7 (plus +8 second pass)
    const int nB = (tid & 31) * 8;      // 0..248

    // compute indices: thread tile 4m x 16n (4 column-quads at n0+64q)
    const int m0 = (tid >> 4) * 4;      // 0..60
    const int n0 = (tid & 15) * 4;      // 0..60

    unsigned long long acc2[4][8];
    #pragma unroll
    for (int i = 0; i < 4; ++i)
        #pragma unroll
        for (int j = 0; j < 8; ++j) acc2[i][j] = 0ULL;

    const float* aPtr = g_AH + (size_t)(mBase + mA) * DD + hA;
    const float* bPtr = Wl + (size_t)kB * DD + nB;

    // prefetch chunk 0
    float4 av  = *(const float4*)(aPtr);
    float4 bv0 = *(const float4*)(bPtr);
    float4 bv1 = *(const float4*)(bPtr + 4);
    float4 bv2 = *(const float4*)(bPtr + 8 * DD);
    float4 bv3 = *(const float4*)(bPtr + 8 * DD + 4);

    for (int kk = 0; kk < DD; kk += 16) {
        As[hA + 0][mA] = av.x; As[hA + 1][mA] = av.y;
        As[hA + 2][mA] = av.z; As[hA + 3][mA] = av.w;
        *(float4*)&Bs[kB][nB]         = bv0;
        *(float4*)&Bs[kB][nB + 4]     = bv1;
        *(float4*)&Bs[kB + 8][nB]     = bv2;
        *(float4*)&Bs[kB + 8][nB + 4] = bv3;
        __syncthreads();

        if (kk + 16 < DD) {
            av  = *(const float4*)(aPtr + kk + 16);
            bv0 = *(const float4*)(bPtr + (size_t)(kk + 16) * DD);
            bv1 = *(const float4*)(bPtr + (size_t)(kk + 16) * DD + 4);
            bv2 = *(const float4*)(bPtr + (size_t)(kk + 24) * DD);
            bv3 = *(const float4*)(bPtr + (size_t)(kk + 24) * DD + 4);
        }

        #pragma unroll
        for (int k = 0; k < 16; ++k) {
            const float4 a0 = *(const float4*)&As[k][m0];
            unsigned long long am2[4];
            am2[0] = pack2(a0.x); am2[1] = pack2(a0.y);
            am2[2] = pack2(a0.z); am2[3] = pack2(a0.w);

            unsigned long long bn2[8];
            #pragma unroll
            for (int q = 0; q < 4; ++q) {
                const ulonglong2 bq = *(const ulonglong2*)&Bs[k][n0 + 64 * q];
                bn2[2 * q + 0] = bq.x;
                bn2[2 * q + 1] = bq.y;
            }

            #pragma unroll
            for (int i = 0; i < 4; ++i)
                #pragma unroll
                for (int j = 0; j < 8; ++j)
                    FMA2(acc2[i][j], am2[i], bn2[j]);
        }
        __syncthreads();
    }

    // fused epilogue: H[row, col] += tanh(acc + bl[col]); refresh bf16 mirror
    float4 blq[4];
    #pragma unroll
    for (int q = 0; q < 4; ++q) blq[q] = *(const float4*)(bl + n0 + 64 * q);

    #pragma unroll
    for (int i = 0; i < 4; ++i) {
        const int m = mBase + m0 + i;
        float*         Hrow  = g_H   + (size_t)m * DD;
        __nv_bfloat16* Hbrow = g_Hbf + (size_t)m * DD;
        #pragma unroll
        for (int q = 0; q < 4; ++q) {
            const int c = n0 + 64 * q;
            float lo0, hi0, lo1, hi1;
            unpack2(acc2[i][2 * q + 0], lo0, hi0);
            unpack2(acc2[i][2 * q + 1], lo1, hi1);
            float4 h = *(float4*)(Hrow + c);
            h.x += tanhf(lo0 + blq[q].x);
            h.y += tanhf(hi0 + blq[q].y);
            h.z += tanhf(lo1 + blq[q].z);
            h.w += tanhf(hi1 + blq[q].w);
            *(float4*)(Hrow + c) = h;
            const __nv_bfloat162 p0 = __floats2bfloat162_rn(h.x, h.y);
            const __nv_bfloat162 p1 = __floats2bfloat162_rn(h.z, h.w);
            uint2 st;
            st.x = *reinterpret_cast<const unsigned*>(&p0);
            st.y = *reinterpret_cast<const unsigned*>(&p1);
            *(uint2*)(Hbrow + c) = st;
        }
    }
}

// =====================================================================
// Kernel 5: decoder. Block = batch. Column sums over nodes (coalesced),
// then tiny GEMV. Reads the fp32 master H.
// =====================================================================
__global__ void __launch_bounds__(256) decoder_kernel(const float* __restrict__ Wd,
                                                      const float* __restrict__ bd,
                                                      float* __restrict__ out) {
    const int b = blockIdx.x;
    const int d = threadIdx.x;
    const float* Hb = g_H + (size_t)b * NN * DD;

    float s0 = 0.f, s1 = 0.f, s2 = 0.f, s3 = 0.f;
    #pragma unroll 1
    for (int n = 0; n < NN; n += 4) {
        s0 += Hb[(size_t)(n + 0) * DD + d];
        s1 += Hb[(size_t)(n + 1) * DD + d];
        s2 += Hb[(size_t)(n + 2) * DD + d];
        s3 += Hb[(size_t)(n + 3) * DD + d];
    }
    __shared__ float mean[DD];
    mean[d] = (s0 + s1 + s2 + s3) * (1.0f / (float)NN);
    __syncthreads();

    if (d < OUTD) {
        float o = bd[d];
        #pragma unroll 8
        for (int k = 0; k < DD; ++k)
            o = fmaf(mean[k], Wd[k * OUTD + d], o);
        out[b * OUTD + d] = o;
    }
}

// =====================================================================
// Launch. Inputs (metadata order): 0 bus_type(i32), 1 Yr, 2 Yi,
// 3 features, 4 W_emb, 5 b_emb, 6 Wl, 7 bl, 8 Wd, 9 bd.
// Output: float[8*15].
// =====================================================================
extern "C" void kernel_launch(void* const* d_in, const int* in_sizes, int n_in,
                              void* d_out, int out_size) {
    const int*   bus_type = (const int*)  d_in[0];
    const float* Yr       = (const float*)d_in[1];
    const float* Yi       = (const float*)d_in[2];
    const float* features = (const float*)d_in[3];
    const float* W_emb    = (const float*)d_in[4];
    const float* b_emb    = (const float*)d_in[5];
    const float* Wl       = (const float*)d_in[6];
    const float* bl       = (const float*)d_in[7];
    const float* Wd       = (const float*)d_in[8];
    const float* bd       = (const float*)d_in[9];
    float* out = (float*)d_out;

    adj_kernel<<<TOTROWS / 8, 256>>>(Yr, Yi);
    emb_kernel<<<TOTROWS, 256>>>(bus_type, features, W_emb, b_emb);

    for (int k = 0; k < KSTEPS; ++k) {
        spmm_kernel<<<TOTROWS / 32, 256>>>();
        update_kernel<<<TOTROWS / 64, 256>>>(Wl, bl);
    }

    decoder_kernel<<<BB, 256>>>(Wd, bd, out);
}

// round 11
// speedup vs baseline: 1.4096x; 1.4096x over previous
#include <cuda_runtime.h>
#include <cuda_bf16.h>

// Problem constants (fixed by reference)
#define BB      8
#define NN      2048
#define DD      256
#define KSTEPS  10
#define OUTD    15
#define MAXN    256
#define TOTROWS (BB * NN)   // 16384

// ---- static device scratch (no allocations allowed) ----
__device__ float          g_H  [TOTROWS * DD];   // 16 MB fp32 master H
__device__ __nv_bfloat16  g_Hbf[TOTROWS * DD];   //  8 MB bf16 mirror (gather source)
__device__ float          g_AH [TOTROWS * DD];   // 16 MB A @ H (tf32-rounded fp32)
__device__ float          g_WlT[DD * DD];        // 256 KB Wl^T (tf32-rounded fp32)
__device__ short          g_col[TOTROWS * MAXN]; //  8 MB padded CSR column indices
__device__ int            g_deg[TOTROWS];
__device__ float          g_inv[TOTROWS];        // 1 / max(deg, 1)

// ---- helpers ----
__device__ __forceinline__ float tf32_round(float x) {
    unsigned u;
    asm("cvt.rna.tf32.f32 %0, %1;" : "=r"(u) : "f"(x));
    return __uint_as_float(u);
}

__device__ __forceinline__ void cp_async16(void* dst, const void* src) {
    unsigned d = (unsigned)__cvta_generic_to_shared(dst);
    asm volatile("cp.async.cg.shared.global [%0], [%1], 16;" :: "r"(d), "l"(src));
}

__device__ __forceinline__ void mma_tf32(float c[4], const unsigned a[4],
                                         const unsigned b0, const unsigned b1) {
    asm volatile(
        "mma.sync.aligned.m16n8k8.row.col.f32.tf32.tf32.f32 "
        "{%0,%1,%2,%3}, {%4,%5,%6,%7}, {%8,%9}, {%0,%1,%2,%3};"
        : "+f"(c[0]), "+f"(c[1]), "+f"(c[2]), "+f"(c[3])
        : "r"(a[0]), "r"(a[1]), "r"(a[2]), "r"(a[3]), "r"(b0), "r"(b1));
}

// =====================================================================
// Kernel 1: adjacency build. One warp per row: ballot-compact nonzero
// columns of (Yr!=0 || Yi!=0), excluding the diagonal. DRAM-bound.
// =====================================================================
__global__ void __launch_bounds__(256) adj_kernel(const float* __restrict__ Yr,
                                                  const float* __restrict__ Yi) {
    const int warp = (blockIdx.x * blockDim.x + threadIdx.x) >> 5; // global row
    const int lane = threadIdx.x & 31;
    if (warp >= TOTROWS) return;
    const int i = warp & (NN - 1);
    const float* yr = Yr + (size_t)warp * NN;
    const float* yi = Yi + (size_t)warp * NN;
    short* cols = g_col + (size_t)warp * MAXN;

    int count = 0;
    #pragma unroll 4
    for (int j0 = 0; j0 < NN; j0 += 32) {
        const int j = j0 + lane;
        const bool nz = (j != i) && ((yr[j] != 0.0f) || (yi[j] != 0.0f));
        const unsigned m = __ballot_sync(0xffffffffu, nz);
        if (nz) {
            const int pos = count + __popc(m & ((1u << lane) - 1u));
            if (pos < MAXN) cols[pos] = (short)j;
        }
        count += __popc(m);
    }
    if (lane == 0) {
        g_deg[warp] = count < MAXN ? count : MAXN;
        g_inv[warp] = 1.0f / (float)(count > 1 ? count : 1);
    }
}

// =====================================================================
// Kernel 2: role-selected embedding. One block per node, thread = d.
// =====================================================================
__global__ void __launch_bounds__(256) emb_kernel(const int*   __restrict__ bus_type,
                                                  const float* __restrict__ features,
                                                  const float* __restrict__ W_emb,
                                                  const float* __restrict__ b_emb) {
    const int node = blockIdx.x;
    const int d = threadIdx.x;
    const int r = bus_type[node] - 1;          // 0..2
    const float f0 = features[node * 2 + 0];
    const float f1 = features[node * 2 + 1];
    const float w0 = W_emb[(r * 2 + 0) * DD + d];
    const float w1 = W_emb[(r * 2 + 1) * DD + d];
    const float h = tanhf(fmaf(f0, w0, fmaf(f1, w1, b_emb[r * DD + d])));
    g_H  [(size_t)node * DD + d] = h;
    g_Hbf[(size_t)node * DD + d] = __float2bfloat16(h);
}

// =====================================================================
// Kernel 2b: Wl^T, tf32-rounded fp32, once. WlT[n][k] = tf32(Wl[k][n]).
// =====================================================================
__global__ void __launch_bounds__(256) wlt_kernel(const float* __restrict__ Wl) {
    const int n = blockIdx.x;
    const int k = threadIdx.x;
    g_WlT[n * DD + k] = tf32_round(Wl[k * DD + n]);
}

// =====================================================================
// Kernel 3: SpMM  AH[row,:] = tf32_round( inv * sum_{j} Hbf[j,:] )
// One warp per row (4 rows sequential). Lane owns d = lane*8..+7.
// bf16 gather / fp32 accumulate / tf32-rounded fp32 store.
// (round-8 unroll-4 form: round 9 showed unroll-8 regresses.)
// =====================================================================
__device__ __forceinline__ void accum_bf16x8(float a[8], const uint4 v) {
    float2 f;
    f = __bfloat1622float2(*reinterpret_cast<const __nv_bfloat162*>(&v.x));
    a[0] += f.x; a[1] += f.y;
    f = __bfloat1622float2(*reinterpret_cast<const __nv_bfloat162*>(&v.y));
    a[2] += f.x; a[3] += f.y;
    f = __bfloat1622float2(*reinterpret_cast<const __nv_bfloat162*>(&v.z));
    a[4] += f.x; a[5] += f.y;
    f = __bfloat1622float2(*reinterpret_cast<const __nv_bfloat162*>(&v.w));
    a[6] += f.x; a[7] += f.y;
}

__global__ void __launch_bounds__(256) spmm_kernel() {
    const int lane = threadIdx.x & 31;
    const int warp = threadIdx.x >> 5;
    const int row0 = blockIdx.x * 32 + warp * 4;

    for (int rr = 0; rr < 4; ++rr) {
        const int row = row0 + rr;
        const int b = row >> 11;
        const __nv_bfloat16* __restrict__ Hb = g_Hbf + (size_t)b * NN * DD;
        const short* __restrict__ cols = g_col + (size_t)row * MAXN;
        const int deg = g_deg[row];
        const float inv = g_inv[row];

        float a[8];
        #pragma unroll
        for (int q = 0; q < 8; ++q) a[q] = 0.0f;

        int t = 0;
        for (; t + 4 <= deg; t += 4) {
            const int j0 = cols[t], j1 = cols[t + 1], j2 = cols[t + 2], j3 = cols[t + 3];
            const uint4 v0 = *((const uint4*)(Hb + (size_t)j0 * DD) + lane);
            const uint4 v1 = *((const uint4*)(Hb + (size_t)j1 * DD) + lane);
            const uint4 v2 = *((const uint4*)(Hb + (size_t)j2 * DD) + lane);
            const uint4 v3 = *((const uint4*)(Hb + (size_t)j3 * DD) + lane);
            accum_bf16x8(a, v0);
            accum_bf16x8(a, v1);
            accum_bf16x8(a, v2);
            accum_bf16x8(a, v3);
        }
        for (; t < deg; ++t) {
            const int j0 = cols[t];
            const uint4 v0 = *((const uint4*)(Hb + (size_t)j0 * DD) + lane);
            accum_bf16x8(a, v0);
        }

        float4* outp = (float4*)(g_AH + (size_t)row * DD);
        outp[lane * 2 + 0] = make_float4(tf32_round(a[0] * inv), tf32_round(a[1] * inv),
                                         tf32_round(a[2] * inv), tf32_round(a[3] * inv));
        outp[lane * 2 + 1] = make_float4(tf32_round(a[4] * inv), tf32_round(a[5] * inv),
                                         tf32_round(a[6] * inv), tf32_round(a[7] * inv));
    }
}

// =====================================================================
// Kernel 4: dense update  H += tanh(AH @ Wl + bl)  via tf32 HMMA
// (mma.sync.m16n8k8, fp32 accum). CTA tile 128m x 128n, grid (128,2),
// 8 warps as 4m x 2n -> warp tile 32m x 64n (2 x 8 mma frags).
// k-chunk 32 loaded with cp.async; SMEM pitch 36 floats so the frag
// LDS pattern (bank = 4*(lane>>2) + (lane&3) + const) is conflict-free.
// Fused epilogue: tanh, += H, bf16 mirror refresh.
// =====================================================================
#define PITCH 36

__global__ void __launch_bounds__(256, 2) update_kernel(const float* __restrict__ bl) {
    __shared__ float As[128 * PITCH];   // [m][k] chunk, 18 KB
    __shared__ float Bs[128 * PITCH];   // [n][k] chunk, 18 KB

    const int tid   = threadIdx.x;
    const int lane  = tid & 31;
    const int wid   = tid >> 5;
    const int mBase = blockIdx.x * 128;
    const int nBase = blockIdx.y * 128;
    const int warpM = (wid & 3) * 32;   // m offset within CTA tile
    const int warpN = (wid >> 2) * 64;  // n offset within CTA tile
    const int gRow  = lane >> 2;        // 0..7
    const int tig   = lane & 3;         // 0..3

    const float* Agbl = g_AH  + (size_t)mBase * DD;
    const float* Bgbl = g_WlT + (size_t)nBase * DD;

    float acc[2][8][4];
    #pragma unroll
    for (int i = 0; i < 2; ++i)
        #pragma unroll
        for (int j = 0; j < 8; ++j)
            #pragma unroll
            for (int q = 0; q < 4; ++q) acc[i][j][q] = 0.0f;

    for (int kk = 0; kk < DD; kk += 32) {
        // async-load the 128x32 A and B chunks (4 x 16B per operand per thread)
        #pragma unroll
        for (int i = 0; i < 4; ++i) {
            const int s   = i * 256 + tid;
            const int row = s >> 3;
            const int kq  = (s & 7) * 4;
            cp_async16(&As[row * PITCH + kq], Agbl + (size_t)row * DD + kk + kq);
            cp_async16(&Bs[row * PITCH + kq], Bgbl + (size_t)row * DD + kk + kq);
        }
        asm volatile("cp.async.commit_group;" ::: "memory");
        asm volatile("cp.async.wait_group 0;" ::: "memory");
        __syncthreads();

        #pragma unroll
        for (int ks = 0; ks < 4; ++ks) {
            const int k8 = ks * 8;

            unsigned a[2][4];
            #pragma unroll
            for (int i = 0; i < 2; ++i) {
                const float* ap = As + (warpM + i * 16 + gRow) * PITCH + k8 + tig;
                a[i][0] = __float_as_uint(ap[0]);
                a[i][1] = __float_as_uint(ap[8 * PITCH]);
                a[i][2] = __float_as_uint(ap[4]);
                a[i][3] = __float_as_uint(ap[8 * PITCH + 4]);
            }

            #pragma unroll
            for (int j = 0; j < 8; ++j) {
                const float* bp = Bs + (warpN + j * 8 + gRow) * PITCH + k8 + tig;
                const unsigned b0 = __float_as_uint(bp[0]);
                const unsigned b1 = __float_as_uint(bp[4]);
                mma_tf32(acc[0][j], a[0], b0, b1);
                mma_tf32(acc[1][j], a[1], b0, b1);
            }
        }
        __syncthreads();
    }

    // fused epilogue: H[m][n] += tanh(acc + bl[n]); refresh bf16 mirror.
    // D frag layout: c0,c1 at (row = lane>>2, col = (lane&3)*2 + {0,1}),
    //                c2,c3 at (row + 8, same cols).
    const int cOff = tig * 2;

    float2 bl2[8];
    #pragma unroll
    for (int j = 0; j < 8; ++j)
        bl2[j] = *(const float2*)(bl + nBase + warpN + j * 8 + cOff);

    #pragma unroll
    for (int i = 0; i < 2; ++i) {
        const int r0 = mBase + warpM + i * 16 + gRow;
        const int r1 = r0 + 8;
        #pragma unroll
        for (int j = 0; j < 8; ++j) {
            const int c = nBase + warpN + j * 8 + cOff;
            const float* ac = acc[i][j];

            float2 h0 = *(float2*)(g_H + (size_t)r0 * DD + c);
            h0.x += tanhf(ac[0] + bl2[j].x);
            h0.y += tanhf(ac[1] + bl2[j].y);
            *(float2*)(g_H + (size_t)r0 * DD + c) = h0;
            const __nv_bfloat162 m0 = __floats2bfloat162_rn(h0.x, h0.y);
            *(unsigned*)(g_Hbf + (size_t)r0 * DD + c) = *reinterpret_cast<const unsigned*>(&m0);

            float2 h1 = *(float2*)(g_H + (size_t)r1 * DD + c);
            h1.x += tanhf(ac[2] + bl2[j].x);
            h1.y += tanhf(ac[3] + bl2[j].y);
            *(float2*)(g_H + (size_t)r1 * DD + c) = h1;
            const __nv_bfloat162 m1 = __floats2bfloat162_rn(h1.x, h1.y);
            *(unsigned*)(g_Hbf + (size_t)r1 * DD + c) = *reinterpret_cast<const unsigned*>(&m1);
        }
    }
}

// =====================================================================
// Kernel 5: decoder. Block = batch. Column sums over nodes (coalesced),
// then tiny GEMV. Reads the fp32 master H.
// =====================================================================
__global__ void __launch_bounds__(256) decoder_kernel(const float* __restrict__ Wd,
                                                      const float* __restrict__ bd,
                                                      float* __restrict__ out) {
    const int b = blockIdx.x;
    const int d = threadIdx.x;
    const float* Hb = g_H + (size_t)b * NN * DD;

    float s0 = 0.f, s1 = 0.f, s2 = 0.f, s3 = 0.f;
    #pragma unroll 1
    for (int n = 0; n < NN; n += 4) {
        s0 += Hb[(size_t)(n + 0) * DD + d];
        s1 += Hb[(size_t)(n + 1) * DD + d];
        s2 += Hb[(size_t)(n + 2) * DD + d];
        s3 += Hb[(size_t)(n + 3) * DD + d];
    }
    __shared__ float mean[DD];
    mean[d] = (s0 + s1 + s2 + s3) * (1.0f / (float)NN);
    __syncthreads();

    if (d < OUTD) {
        float o = bd[d];
        #pragma unroll 8
        for (int k = 0; k < DD; ++k)
            o = fmaf(mean[k], Wd[k * OUTD + d], o);
        out[b * OUTD + d] = o;
    }
}

// =====================================================================
// Launch. Inputs (metadata order): 0 bus_type(i32), 1 Yr, 2 Yi,
// 3 features, 4 W_emb, 5 b_emb, 6 Wl, 7 bl, 8 Wd, 9 bd.
// Output: float[8*15].
// =====================================================================
extern "C" void kernel_launch(void* const* d_in, const int* in_sizes, int n_in,
                              void* d_out, int out_size) {
    const int*   bus_type = (const int*)  d_in[0];
    const float* Yr       = (const float*)d_in[1];
    const float* Yi       = (const float*)d_in[2];
    const float* features = (const float*)d_in[3];
    const float* W_emb    = (const float*)d_in[4];
    const float* b_emb    = (const float*)d_in[5];
    const float* Wl       = (const float*)d_in[6];
    const float* bl       = (const float*)d_in[7];
    const float* Wd       = (const float*)d_in[8];
    const float* bd       = (const float*)d_in[9];
    float* out = (float*)d_out;

    adj_kernel<<<TOTROWS / 8, 256>>>(Yr, Yi);
    emb_kernel<<<TOTROWS, 256>>>(bus_type, features, W_emb, b_emb);
    wlt_kernel<<<DD, DD>>>(Wl);

    for (int k = 0; k < KSTEPS; ++k) {
        spmm_kernel<<<TOTROWS / 32, 256>>>();
        update_kernel<<<dim3(TOTROWS / 128, 2), 256>>>(bl);
    }

    decoder_kernel<<<BB, 256>>>(Wd, bd, out);
}

// round 12
// speedup vs baseline: 1.5511x; 1.1004x over previous
#include <cuda_runtime.h>
#include <cuda_bf16.h>

// Problem constants (fixed by reference)
#define BB      8
#define NN      2048
#define DD      256
#define KSTEPS  10
#define OUTD    15
#define MAXN    256
#define TOTROWS (BB * NN)   // 16384

// ---- static device scratch (no allocations allowed) ----
// NOTE: g_AH and g_WlT are stored K-PERMUTED: within each group of 8
// consecutive k-columns, element k goes to slot (k&3)*2 + ((k>>2)&1).
// This makes every tf32 mma fragment read a single LDS.64 of (k, k+4).
__device__ float          g_H  [TOTROWS * DD];   // 16 MB fp32 master H
__device__ __nv_bfloat16  g_Hbf[TOTROWS * DD];   //  8 MB bf16 mirror (gather source)
__device__ float          g_AH [TOTROWS * DD];   // 16 MB A @ H (tf32, k-permuted)
__device__ float          g_WlT[DD * DD];        // 256 KB Wl^T (tf32, k-permuted)
__device__ short          g_col[TOTROWS * MAXN]; //  8 MB padded CSR column indices
__device__ int            g_deg[TOTROWS];
__device__ float          g_inv[TOTROWS];        // 1 / max(deg, 1)

// ---- helpers ----
__device__ __forceinline__ float tf32_round(float x) {
    unsigned u;
    asm("cvt.rna.tf32.f32 %0, %1;" : "=r"(u) : "f"(x));
    return __uint_as_float(u);
}

__device__ __forceinline__ void cp_async16(void* dst, const void* src) {
    unsigned d = (unsigned)__cvta_generic_to_shared(dst);
    asm volatile("cp.async.cg.shared.global [%0], [%1], 16;" :: "r"(d), "l"(src));
}

__device__ __forceinline__ void mma_tf32(float c[4], const unsigned a[4],
                                         const unsigned b0, const unsigned b1) {
    asm volatile(
        "mma.sync.aligned.m16n8k8.row.col.f32.tf32.tf32.f32 "
        "{%0,%1,%2,%3}, {%4,%5,%6,%7}, {%8,%9}, {%0,%1,%2,%3};"
        : "+f"(c[0]), "+f"(c[1]), "+f"(c[2]), "+f"(c[3])
        : "r"(a[0]), "r"(a[1]), "r"(a[2]), "r"(a[3]), "r"(b0), "r"(b1));
}

// bf16x2 -> two f32 via byte-permute, accumulate with one packed f32x2 add.
__device__ __forceinline__ void acc_bf16x2(unsigned long long& acc, unsigned u) {
    const unsigned lo = __byte_perm(u, 0, 0x1044);   // {u.b1,u.b0,0,0}
    const unsigned hi = __byte_perm(u, 0, 0x3244);   // {u.b3,u.b2,0,0}
    unsigned long long v;
    asm("mov.b64 %0, {%1, %2};" : "=l"(v) : "r"(lo), "r"(hi));
    asm("add.rn.f32x2 %0, %0, %1;" : "+l"(acc) : "l"(v));
}

__device__ __forceinline__ void unpack2(unsigned long long v, float& lo, float& hi) {
    unsigned a, b;
    asm("mov.b64 {%0, %1}, %2;" : "=r"(a), "=r"(b) : "l"(v));
    lo = __uint_as_float(a);
    hi = __uint_as_float(b);
}

// =====================================================================
// Kernel 1: adjacency build. One warp per row: ballot-compact nonzero
// columns of (Yr!=0 || Yi!=0), excluding the diagonal. DRAM-bound.
// =====================================================================
__global__ void __launch_bounds__(256) adj_kernel(const float* __restrict__ Yr,
                                                  const float* __restrict__ Yi) {
    const int warp = (blockIdx.x * blockDim.x + threadIdx.x) >> 5; // global row
    const int lane = threadIdx.x & 31;
    if (warp >= TOTROWS) return;
    const int i = warp & (NN - 1);
    const float* yr = Yr + (size_t)warp * NN;
    const float* yi = Yi + (size_t)warp * NN;
    short* cols = g_col + (size_t)warp * MAXN;

    int count = 0;
    #pragma unroll 4
    for (int j0 = 0; j0 < NN; j0 += 32) {
        const int j = j0 + lane;
        const bool nz = (j != i) && ((yr[j] != 0.0f) || (yi[j] != 0.0f));
        const unsigned m = __ballot_sync(0xffffffffu, nz);
        if (nz) {
            const int pos = count + __popc(m & ((1u << lane) - 1u));
            if (pos < MAXN) cols[pos] = (short)j;
        }
        count += __popc(m);
    }
    if (lane == 0) {
        g_deg[warp] = count < MAXN ? count : MAXN;
        g_inv[warp] = 1.0f / (float)(count > 1 ? count : 1);
    }
}

// =====================================================================
// Kernel 2: role-selected embedding. One block per node, thread = d.
// =====================================================================
__global__ void __launch_bounds__(256) emb_kernel(const int*   __restrict__ bus_type,
                                                  const float* __restrict__ features,
                                                  const float* __restrict__ W_emb,
                                                  const float* __restrict__ b_emb) {
    const int node = blockIdx.x;
    const int d = threadIdx.x;
    const int r = bus_type[node] - 1;          // 0..2
    const float f0 = features[node * 2 + 0];
    const float f1 = features[node * 2 + 1];
    const float w0 = W_emb[(r * 2 + 0) * DD + d];
    const float w1 = W_emb[(r * 2 + 1) * DD + d];
    const float h = tanhf(fmaf(f0, w0, fmaf(f1, w1, b_emb[r * DD + d])));
    g_H  [(size_t)node * DD + d] = h;
    g_Hbf[(size_t)node * DD + d] = __float2bfloat16(h);
}

// =====================================================================
// Kernel 2b: Wl^T, tf32-rounded, k-permuted. WlT[n][perm(k)] = Wl[k][n].
// =====================================================================
__global__ void __launch_bounds__(256) wlt_kernel(const float* __restrict__ Wl) {
    const int n = blockIdx.x;
    const int k = threadIdx.x;
    const int t = k & 7;
    const int kp = (k & ~7) | ((t & 3) * 2 + (t >> 2));
    g_WlT[n * DD + kp] = tf32_round(Wl[k * DD + n]);
}

// =====================================================================
// Kernel 3: SpMM  AH[row,:] = tf32( inv * sum_{j} Hbf[j,:] ), k-permuted.
// ONE warp per row (grid TOTROWS/8: round-11 grid of 512 capped occ at
// 3.5 CTA/SM). Lane owns d = lane*8..+7. bf16 gather; PRMT + packed
// f32x2 adds cut accumulate issue count from 16 to 12 per 16B.
// =====================================================================
__device__ __forceinline__ void accum16(unsigned long long acc[4], const uint4 v) {
    acc_bf16x2(acc[0], v.x);
    acc_bf16x2(acc[1], v.y);
    acc_bf16x2(acc[2], v.z);
    acc_bf16x2(acc[3], v.w);
}

__global__ void __launch_bounds__(256) spmm_kernel() {
    const int lane = threadIdx.x & 31;
    const int row  = blockIdx.x * 8 + (threadIdx.x >> 5);
    const int b = row >> 11;
    const __nv_bfloat16* __restrict__ Hb = g_Hbf + (size_t)b * NN * DD;
    const short* __restrict__ cols = g_col + (size_t)row * MAXN;
    const int deg = g_deg[row];
    const float inv = g_inv[row];

    unsigned long long acc[4];
    #pragma unroll
    for (int q = 0; q < 4; ++q) acc[q] = 0ULL;

    int t = 0;
    for (; t + 4 <= deg; t += 4) {
        const ushort4 j4 = *(const ushort4*)(cols + t);   // one 8B idx load / 4 nbrs
        const uint4 v0 = *((const uint4*)(Hb + (size_t)j4.x * DD) + lane);
        const uint4 v1 = *((const uint4*)(Hb + (size_t)j4.y * DD) + lane);
        const uint4 v2 = *((const uint4*)(Hb + (size_t)j4.z * DD) + lane);
        const uint4 v3 = *((const uint4*)(Hb + (size_t)j4.w * DD) + lane);
        accum16(acc, v0);
        accum16(acc, v1);
        accum16(acc, v2);
        accum16(acc, v3);
    }
    for (; t < deg; ++t) {
        const int j0 = cols[t];
        const uint4 v0 = *((const uint4*)(Hb + (size_t)j0 * DD) + lane);
        accum16(acc, v0);
    }

    float a[8];
    unpack2(acc[0], a[0], a[1]);
    unpack2(acc[1], a[2], a[3]);
    unpack2(acc[2], a[4], a[5]);
    unpack2(acc[3], a[6], a[7]);
    #pragma unroll
    for (int q = 0; q < 8; ++q) a[q] = tf32_round(a[q] * inv);

    // k-permuted store: slot order within the k8 group = a0,a4,a1,a5,a2,a6,a3,a7
    float4* outp = (float4*)(g_AH + (size_t)row * DD);
    outp[lane * 2 + 0] = make_float4(a[0], a[4], a[1], a[5]);
    outp[lane * 2 + 1] = make_float4(a[2], a[6], a[3], a[7]);
}

// =====================================================================
// Kernel 4: dense update  H += tanh(AH @ Wl + bl)  via tf32 HMMA
// (mma.sync.m16n8k8, fp32 accum). CTA tile 128m x 128n, grid (128,2),
// 8 warps as 4m x 2n -> warp tile 32m x 64n. k-chunk 32 via cp.async.
// Operands are k-permuted by the producers, so every fragment read is
// one LDS.64 of the (k, k+4) pair: 12 LDS.64 per 16 MMA per k8 (was 24
// LDS.32). PITCH 40 -> bank = 4*gRow + tig, conflict-free per phase.
// Fused epilogue: tanh, += H, bf16 mirror refresh.
// =====================================================================
#define PITCH 40

__global__ void __launch_bounds__(256, 2) update_kernel(const float* __restrict__ bl) {
    __shared__ float As[128 * PITCH];   // [m][k-permuted] chunk, 20 KB
    __shared__ float Bs[128 * PITCH];   // [n][k-permuted] chunk, 20 KB

    const int tid   = threadIdx.x;
    const int lane  = tid & 31;
    const int wid   = tid >> 5;
    const int mBase = blockIdx.x * 128;
    const int nBase = blockIdx.y * 128;
    const int warpM = (wid & 3) * 32;   // m offset within CTA tile
    const int warpN = (wid >> 2) * 64;  // n offset within CTA tile
    const int gRow  = lane >> 2;        // 0..7
    const int tig   = lane & 3;         // 0..3

    const float* Agbl = g_AH  + (size_t)mBase * DD;
    const float* Bgbl = g_WlT + (size_t)nBase * DD;

    float acc[2][8][4];
    #pragma unroll
    for (int i = 0; i < 2; ++i)
        #pragma unroll
        for (int j = 0; j < 8; ++j)
            #pragma unroll
            for (int q = 0; q < 4; ++q) acc[i][j][q] = 0.0f;

    for (int kk = 0; kk < DD; kk += 32) {
        // async-load the 128x32 A and B chunks (4 x 16B per operand per thread)
        #pragma unroll
        for (int i = 0; i < 4; ++i) {
            const int s   = i * 256 + tid;
            const int row = s >> 3;
            const int kq  = (s & 7) * 4;
            cp_async16(&As[row * PITCH + kq], Agbl + (size_t)row * DD + kk + kq);
            cp_async16(&Bs[row * PITCH + kq], Bgbl + (size_t)row * DD + kk + kq);
        }
        asm volatile("cp.async.commit_group;" ::: "memory");
        asm volatile("cp.async.wait_group 0;" ::: "memory");
        __syncthreads();

        #pragma unroll
        for (int ks = 0; ks < 4; ++ks) {
            const int k8 = ks * 8;

            unsigned a[2][4];
            #pragma unroll
            for (int i = 0; i < 2; ++i) {
                const float* ap = As + (warpM + i * 16 + gRow) * PITCH + k8 + 2 * tig;
                const float2 w0 = *(const float2*)ap;               // (k=tig, k=tig+4)
                const float2 w1 = *(const float2*)(ap + 8 * PITCH); // row+8
                a[i][0] = __float_as_uint(w0.x);
                a[i][1] = __float_as_uint(w1.x);
                a[i][2] = __float_as_uint(w0.y);
                a[i][3] = __float_as_uint(w1.y);
            }

            #pragma unroll
            for (int j = 0; j < 8; ++j) {
                const float* bp = Bs + (warpN + j * 8 + gRow) * PITCH + k8 + 2 * tig;
                const float2 bw = *(const float2*)bp;               // (b0, b1)
                const unsigned b0 = __float_as_uint(bw.x);
                const unsigned b1 = __float_as_uint(bw.y);
                mma_tf32(acc[0][j], a[0], b0, b1);
                mma_tf32(acc[1][j], a[1], b0, b1);
            }
        }
        __syncthreads();
    }

    // fused epilogue: H[m][n] += tanh(acc + bl[n]); refresh bf16 mirror.
    const int cOff = tig * 2;

    float2 bl2[8];
    #pragma unroll
    for (int j = 0; j < 8; ++j)
        bl2[j] = *(const float2*)(bl + nBase + warpN + j * 8 + cOff);

    #pragma unroll
    for (int i = 0; i < 2; ++i) {
        const int r0 = mBase + warpM + i * 16 + gRow;
        const int r1 = r0 + 8;
        #pragma unroll
        for (int j = 0; j < 8; ++j) {
            const int c = nBase + warpN + j * 8 + cOff;
            const float* ac = acc[i][j];

            float2 h0 = *(float2*)(g_H + (size_t)r0 * DD + c);
            h0.x += tanhf(ac[0] + bl2[j].x);
            h0.y += tanhf(ac[1] + bl2[j].y);
            *(float2*)(g_H + (size_t)r0 * DD + c) = h0;
            const __nv_bfloat162 m0 = __floats2bfloat162_rn(h0.x, h0.y);
            *(unsigned*)(g_Hbf + (size_t)r0 * DD + c) = *reinterpret_cast<const unsigned*>(&m0);

            float2 h1 = *(float2*)(g_H + (size_t)r1 * DD + c);
            h1.x += tanhf(ac[2] + bl2[j].x);
            h1.y += tanhf(ac[3] + bl2[j].y);
            *(float2*)(g_H + (size_t)r1 * DD + c) = h1;
            const __nv_bfloat162 m1 = __floats2bfloat162_rn(h1.x, h1.y);
            *(unsigned*)(g_Hbf + (size_t)r1 * DD + c) = *reinterpret_cast<const unsigned*>(&m1);
        }
    }
}

// =====================================================================
// Kernel 5: decoder. Block = batch. Column sums over nodes (coalesced),
// then tiny GEMV. Reads the fp32 master H.
// =====================================================================
__global__ void __launch_bounds__(256) decoder_kernel(const float* __restrict__ Wd,
                                                      const float* __restrict__ bd,
                                                      float* __restrict__ out) {
    const int b = blockIdx.x;
    const int d = threadIdx.x;
    const float* Hb = g_H + (size_t)b * NN * DD;

    float s0 = 0.f, s1 = 0.f, s2 = 0.f, s3 = 0.f;
    #pragma unroll 1
    for (int n = 0; n < NN; n += 4) {
        s0 += Hb[(size_t)(n + 0) * DD + d];
        s1 += Hb[(size_t)(n + 1) * DD + d];
        s2 += Hb[(size_t)(n + 2) * DD + d];
        s3 += Hb[(size_t)(n + 3) * DD + d];
    }
    __shared__ float mean[DD];
    mean[d] = (s0 + s1 + s2 + s3) * (1.0f / (float)NN);
    __syncthreads();

    if (d < OUTD) {
        float o = bd[d];
        #pragma unroll 8
        for (int k = 0; k < DD; ++k)
            o = fmaf(mean[k], Wd[k * OUTD + d], o);
        out[b * OUTD + d] = o;
    }
}

// =====================================================================
// Launch. Inputs (metadata order): 0 bus_type(i32), 1 Yr, 2 Yi,
// 3 features, 4 W_emb, 5 b_emb, 6 Wl, 7 bl, 8 Wd, 9 bd.
// Output: float[8*15].
// =====================================================================
extern "C" void kernel_launch(void* const* d_in, const int* in_sizes, int n_in,
                              void* d_out, int out_size) {
    const int*   bus_type = (const int*)  d_in[0];
    const float* Yr       = (const float*)d_in[1];
    const float* Yi       = (const float*)d_in[2];
    const float* features = (const float*)d_in[3];
    const float* W_emb    = (const float*)d_in[4];
    const float* b_emb    = (const float*)d_in[5];
    const float* Wl       = (const float*)d_in[6];
    const float* bl       = (const float*)d_in[7];
    const float* Wd       = (const float*)d_in[8];
    const float* bd       = (const float*)d_in[9];
    float* out = (float*)d_out;

    adj_kernel<<<TOTROWS / 8, 256>>>(Yr, Yi);
    emb_kernel<<<TOTROWS, 256>>>(bus_type, features, W_emb, b_emb);
    wlt_kernel<<<DD, DD>>>(Wl);

    for (int k = 0; k < KSTEPS; ++k) {
        spmm_kernel<<<TOTROWS / 8, 256>>>();
        update_kernel<<<dim3(TOTROWS / 128, 2), 256>>>(bl);
    }

    decoder_kernel<<<BB, 256>>>(Wd, bd, out);
}

// round 14
// speedup vs baseline: 1.6629x; 1.0721x over previous
#include <cuda_runtime.h>
#include <cuda_bf16.h>

// Problem constants (fixed by reference)
#define BB      8
#define NN      2048
#define DD      256
#define KSTEPS  10
#define OUTD    15
#define MAXN    256
#define TOTROWS (BB * NN)   // 16384

// ---- static device scratch (no allocations allowed) ----
// NOTE: g_AH and g_WlT are stored K-PERMUTED: within each group of 8
// consecutive k-columns, element k goes to slot (k&3)*2 + ((k>>2)&1).
// This makes every tf32 mma fragment read a single LDS.64 of (k, k+4).
__device__ float          g_H  [TOTROWS * DD];   // 16 MB fp32 master H
__device__ __nv_bfloat16  g_Hbf[TOTROWS * DD];   //  8 MB bf16 mirror (gather source)
__device__ float          g_AH [TOTROWS * DD];   // 16 MB A @ H (tf32, k-permuted)
__device__ float          g_WlT[DD * DD];        // 256 KB Wl^T (tf32, k-permuted)
__device__ short          g_col[TOTROWS * MAXN]; //  8 MB padded CSR column indices
__device__ int            g_deg[TOTROWS];
__device__ float          g_inv[TOTROWS];        // 1 / max(deg, 1)

// ---- helpers ----
__device__ __forceinline__ float tf32_round(float x) {
    unsigned u;
    asm("cvt.rna.tf32.f32 %0, %1;" : "=r"(u) : "f"(x));
    return __uint_as_float(u);
}

__device__ __forceinline__ void cp_async16(void* dst, const void* src) {
    unsigned d = (unsigned)__cvta_generic_to_shared(dst);
    asm volatile("cp.async.cg.shared.global [%0], [%1], 16;" :: "r"(d), "l"(src));
}

__device__ __forceinline__ void mma_tf32(float c[4], const unsigned a[4],
                                         const unsigned b0, const unsigned b1) {
    asm volatile(
        "mma.sync.aligned.m16n8k8.row.col.f32.tf32.tf32.f32 "
        "{%0,%1,%2,%3}, {%4,%5,%6,%7}, {%8,%9}, {%0,%1,%2,%3};"
        : "+f"(c[0]), "+f"(c[1]), "+f"(c[2]), "+f"(c[3])
        : "r"(a[0]), "r"(a[1]), "r"(a[2]), "r"(a[3]), "r"(b0), "r"(b1));
}

// bf16x2 -> two f32 via byte-permute, accumulate with one packed f32x2 add.
__device__ __forceinline__ void acc_bf16x2(unsigned long long& acc, unsigned u) {
    const unsigned lo = __byte_perm(u, 0, 0x1044);   // {u.b1,u.b0,0,0}
    const unsigned hi = __byte_perm(u, 0, 0x3244);   // {u.b3,u.b2,0,0}
    unsigned long long v;
    asm("mov.b64 %0, {%1, %2};" : "=l"(v) : "r"(lo), "r"(hi));
    asm("add.rn.f32x2 %0, %0, %1;" : "+l"(acc) : "l"(v));
}

__device__ __forceinline__ void unpack2(unsigned long long v, float& lo, float& hi) {
    unsigned a, b;
    asm("mov.b64 {%0, %1}, %2;" : "=r"(a), "=r"(b) : "l"(v));
    lo = __uint_as_float(a);
    hi = __uint_as_float(b);
}

// =====================================================================
// Kernel 1: adjacency build. One warp per row: ballot-compact nonzero
// columns of (Yr!=0 || Yi!=0), excluding the diagonal. DRAM-bound.
// =====================================================================
__global__ void __launch_bounds__(256) adj_kernel(const float* __restrict__ Yr,
                                                  const float* __restrict__ Yi) {
    const int warp = (blockIdx.x * blockDim.x + threadIdx.x) >> 5; // global row
    const int lane = threadIdx.x & 31;
    if (warp >= TOTROWS) return;
    const int i = warp & (NN - 1);
    const float* yr = Yr + (size_t)warp * NN;
    const float* yi = Yi + (size_t)warp * NN;
    short* cols = g_col + (size_t)warp * MAXN;

    int count = 0;
    #pragma unroll 4
    for (int j0 = 0; j0 < NN; j0 += 32) {
        const int j = j0 + lane;
        const bool nz = (j != i) && ((yr[j] != 0.0f) || (yi[j] != 0.0f));
        const unsigned m = __ballot_sync(0xffffffffu, nz);
        if (nz) {
            const int pos = count + __popc(m & ((1u << lane) - 1u));
            if (pos < MAXN) cols[pos] = (short)j;
        }
        count += __popc(m);
    }
    if (lane == 0) {
        g_deg[warp] = count < MAXN ? count : MAXN;
        g_inv[warp] = 1.0f / (float)(count > 1 ? count : 1);
    }
}

// =====================================================================
// Kernel 2: role-selected embedding. One block per node, thread = d.
// =====================================================================
__global__ void __launch_bounds__(256) emb_kernel(const int*   __restrict__ bus_type,
                                                  const float* __restrict__ features,
                                                  const float* __restrict__ W_emb,
                                                  const float* __restrict__ b_emb) {
    const int node = blockIdx.x;
    const int d = threadIdx.x;
    const int r = bus_type[node] - 1;          // 0..2
    const float f0 = features[node * 2 + 0];
    const float f1 = features[node * 2 + 1];
    const float w0 = W_emb[(r * 2 + 0) * DD + d];
    const float w1 = W_emb[(r * 2 + 1) * DD + d];
    const float h = tanhf(fmaf(f0, w0, fmaf(f1, w1, b_emb[r * DD + d])));
    g_H  [(size_t)node * DD + d] = h;
    g_Hbf[(size_t)node * DD + d] = __float2bfloat16(h);
}

// =====================================================================
// Kernel 2b: Wl^T, tf32-rounded, k-permuted. WlT[n][perm(k)] = Wl[k][n].
// =====================================================================
__global__ void __launch_bounds__(256) wlt_kernel(const float* __restrict__ Wl) {
    const int n = blockIdx.x;
    const int k = threadIdx.x;
    const int t = k & 7;
    const int kp = (k & ~7) | ((t & 3) * 2 + (t >> 2));
    g_WlT[n * DD + kp] = tf32_round(Wl[k * DD + n]);
}

// =====================================================================
// Kernel 3: SpMM  AH[row,:] = tf32( inv * sum_{j} Hbf[j,:] ), k-permuted.
// One warp per row. Lane owns d = lane*8..+7. bf16 gather; PRMT +
// packed f32x2 adds. Index quads are software-pipelined.
// =====================================================================
__device__ __forceinline__ void accum16(unsigned long long acc[4], const uint4 v) {
    acc_bf16x2(acc[0], v.x);
    acc_bf16x2(acc[1], v.y);
    acc_bf16x2(acc[2], v.z);
    acc_bf16x2(acc[3], v.w);
}

__global__ void __launch_bounds__(256) spmm_kernel() {
    const int lane = threadIdx.x & 31;
    const int row  = blockIdx.x * 8 + (threadIdx.x >> 5);
    const int b = row >> 11;
    const __nv_bfloat16* __restrict__ Hb = g_Hbf + (size_t)b * NN * DD;
    const short* __restrict__ cols = g_col + (size_t)row * MAXN;
    const int deg = g_deg[row];
    const float inv = g_inv[row];

    unsigned long long acc[4];
    #pragma unroll
    for (int q = 0; q < 4; ++q) acc[q] = 0ULL;

    int t = 0;
    if (deg >= 4) {
        ushort4 j4 = *(const ushort4*)(cols);     // prefetched quad
        for (; t + 8 <= deg; t += 4) {
            const ushort4 jn = *(const ushort4*)(cols + t + 4);  // next quad
            const uint4 v0 = *((const uint4*)(Hb + (size_t)j4.x * DD) + lane);
            const uint4 v1 = *((const uint4*)(Hb + (size_t)j4.y * DD) + lane);
            const uint4 v2 = *((const uint4*)(Hb + (size_t)j4.z * DD) + lane);
            const uint4 v3 = *((const uint4*)(Hb + (size_t)j4.w * DD) + lane);
            accum16(acc, v0);
            accum16(acc, v1);
            accum16(acc, v2);
            accum16(acc, v3);
            j4 = jn;
        }
        // last full quad
        const uint4 v0 = *((const uint4*)(Hb + (size_t)j4.x * DD) + lane);
        const uint4 v1 = *((const uint4*)(Hb + (size_t)j4.y * DD) + lane);
        const uint4 v2 = *((const uint4*)(Hb + (size_t)j4.z * DD) + lane);
        const uint4 v3 = *((const uint4*)(Hb + (size_t)j4.w * DD) + lane);
        accum16(acc, v0);
        accum16(acc, v1);
        accum16(acc, v2);
        accum16(acc, v3);
        t += 4;
    }
    for (; t < deg; ++t) {
        const int j0 = cols[t];
        const uint4 v0 = *((const uint4*)(Hb + (size_t)j0 * DD) + lane);
        accum16(acc, v0);
    }

    float a[8];
    unpack2(acc[0], a[0], a[1]);
    unpack2(acc[1], a[2], a[3]);
    unpack2(acc[2], a[4], a[5]);
    unpack2(acc[3], a[6], a[7]);
    #pragma unroll
    for (int q = 0; q < 8; ++q) a[q] = tf32_round(a[q] * inv);

    // k-permuted store: slot order within the k8 group = a0,a4,a1,a5,a2,a6,a3,a7
    float4* outp = (float4*)(g_AH + (size_t)row * DD);
    outp[lane * 2 + 0] = make_float4(a[0], a[4], a[1], a[5]);
    outp[lane * 2 + 1] = make_float4(a[2], a[6], a[3], a[7]);
}

// =====================================================================
// Kernel 4: dense update  H += tanh(AH @ Wl + bl)  via tf32 HMMA
// (mma.sync.m16n8k8, fp32 accum). CTA tile 128m x 128n, grid (128,2),
// 8 warps as 4m x 2n -> warp tile 32m x 64n.
// 2-stage double-buffered cp.async pipeline, k-chunk 16 (16 chunks),
// one __syncthreads per chunk; chunk c+1 loads fly during compute of c.
// SMEM: PITCH 16 (zero pad), XOR-4 swizzle on 64-bit words
// (phys_w = w ^ (((row>>1)&1)<<2)); at write time this is a 16B-segment
// swizzle physSeg = seg ^ (((row>>1)&1)<<1). Applied at write AND read:
// numerics bit-identical to the k-permuted linear layout.
// FIX vs r13: load mapping is row = s>>2, seg = s&3 (4 segs/row); the
// r13 mapping (row = s>>1) indexed rows 128..255 -> OOB global reads.
// Fused epilogue: tanh, += H, bf16 mirror refresh.
// =====================================================================
__global__ void __launch_bounds__(256, 2) update_kernel(const float* __restrict__ bl) {
    __shared__ float As[2][128 * 16];   // 8 KB per stage
    __shared__ float Bs[2][128 * 16];

    const int tid   = threadIdx.x;
    const int lane  = tid & 31;
    const int wid   = tid >> 5;
    const int mBase = blockIdx.x * 128;
    const int nBase = blockIdx.y * 128;
    const int warpM = (wid & 3) * 32;   // m offset within CTA tile
    const int warpN = (wid >> 2) * 64;  // n offset within CTA tile
    const int gRow  = lane >> 2;        // 0..7
    const int tig   = lane & 3;         // 0..3
    const int swzR  = ((gRow >> 1) & 1) << 2;   // read-side swizzle (64b-word XOR)

    const float* Agbl = g_AH  + (size_t)mBase * DD;
    const float* Bgbl = g_WlT + (size_t)nBase * DD;

    // load mapping: 512 16B-segments per operand per chunk, 2 per thread.
    // s in {tid, tid+256}; row = s>>2 (0..127), seg = s&3 (0..3).
    const int ldRow0 = tid >> 2;
    const int ldSeg0 = tid & 3;
    const int ldRow1 = (tid + 256) >> 2;
    const int ldSeg1 = ldSeg0;   // (tid+256)&3 == tid&3
    // physical 16B segment after swizzle; float offset = physSeg*4
    const int ldOff0 = ldRow0 * 16 + (ldSeg0 ^ (((ldRow0 >> 1) & 1) << 1)) * 4;
    const int ldOff1 = ldRow1 * 16 + (ldSeg1 ^ (((ldRow1 >> 1) & 1) << 1)) * 4;
    const int ldSrc0 = ldRow0 * DD + ldSeg0 * 4;
    const int ldSrc1 = ldRow1 * DD + ldSeg1 * 4;

    float acc[2][8][4];
    #pragma unroll
    for (int i = 0; i < 2; ++i)
        #pragma unroll
        for (int j = 0; j < 8; ++j)
            #pragma unroll
            for (int q = 0; q < 4; ++q) acc[i][j][q] = 0.0f;

    // prologue: issue chunk 0 into stage 0
    cp_async16(&As[0][ldOff0], Agbl + ldSrc0);
    cp_async16(&As[0][ldOff1], Agbl + ldSrc1);
    cp_async16(&Bs[0][ldOff0], Bgbl + ldSrc0);
    cp_async16(&Bs[0][ldOff1], Bgbl + ldSrc1);
    asm volatile("cp.async.commit_group;" ::: "memory");

    #pragma unroll
    for (int c = 0; c < 16; ++c) {
        const int st = c & 1;
        asm volatile("cp.async.wait_group 0;" ::: "memory");
        __syncthreads();

        if (c + 1 < 16) {
            const int kk = (c + 1) * 16;
            const int nx = st ^ 1;
            cp_async16(&As[nx][ldOff0], Agbl + kk + ldSrc0);
            cp_async16(&As[nx][ldOff1], Agbl + kk + ldSrc1);
            cp_async16(&Bs[nx][ldOff0], Bgbl + kk + ldSrc0);
            cp_async16(&Bs[nx][ldOff1], Bgbl + kk + ldSrc1);
            asm volatile("cp.async.commit_group;" ::: "memory");
        }

        #pragma unroll
        for (int ks = 0; ks < 2; ++ks) {
            // 64-bit word w = ks*4 + tig, swizzled; float offset = phys*2
            const int fOff = ((ks * 4 + tig) ^ swzR) * 2;

            unsigned a[2][4];
            #pragma unroll
            for (int i = 0; i < 2; ++i) {
                const float* ap = &As[st][(warpM + i * 16 + gRow) * 16 + fOff];
                const float2 w0 = *(const float2*)ap;            // (k=tig, k=tig+4)
                const float2 w1 = *(const float2*)(ap + 8 * 16); // row+8 (same swizzle)
                a[i][0] = __float_as_uint(w0.x);
                a[i][1] = __float_as_uint(w1.x);
                a[i][2] = __float_as_uint(w0.y);
                a[i][3] = __float_as_uint(w1.y);
            }

            #pragma unroll
            for (int j = 0; j < 8; ++j) {
                const float* bp = &Bs[st][(warpN + j * 8 + gRow) * 16 + fOff];
                const float2 bw = *(const float2*)bp;
                const unsigned b0 = __float_as_uint(bw.x);
                const unsigned b1 = __float_as_uint(bw.y);
                mma_tf32(acc[0][j], a[0], b0, b1);
                mma_tf32(acc[1][j], a[1], b0, b1);
            }
        }
    }

    // fused epilogue: H[m][n] += tanh(acc + bl[n]); refresh bf16 mirror.
    const int cOff = tig * 2;

    float2 bl2[8];
    #pragma unroll
    for (int j = 0; j < 8; ++j)
        bl2[j] = *(const float2*)(bl + nBase + warpN + j * 8 + cOff);

    #pragma unroll
    for (int i = 0; i < 2; ++i) {
        const int r0 = mBase + warpM + i * 16 + gRow;
        const int r1 = r0 + 8;
        #pragma unroll
        for (int j = 0; j < 8; ++j) {
            const int c = nBase + warpN + j * 8 + cOff;
            const float* ac = acc[i][j];

            float2 h0 = *(float2*)(g_H + (size_t)r0 * DD + c);
            h0.x += tanhf(ac[0] + bl2[j].x);
            h0.y += tanhf(ac[1] + bl2[j].y);
            *(float2*)(g_H + (size_t)r0 * DD + c) = h0;
            const __nv_bfloat162 m0 = __floats2bfloat162_rn(h0.x, h0.y);
            *(unsigned*)(g_Hbf + (size_t)r0 * DD + c) = *reinterpret_cast<const unsigned*>(&m0);

            float2 h1 = *(float2*)(g_H + (size_t)r1 * DD + c);
            h1.x += tanhf(ac[2] + bl2[j].x);
            h1.y += tanhf(ac[3] + bl2[j].y);
            *(float2*)(g_H + (size_t)r1 * DD + c) = h1;
            const __nv_bfloat162 m1 = __floats2bfloat162_rn(h1.x, h1.y);
            *(unsigned*)(g_Hbf + (size_t)r1 * DD + c) = *reinterpret_cast<const unsigned*>(&m1);
        }
    }
}

// =====================================================================
// Kernel 5: decoder. Block = batch. Column sums over nodes (coalesced),
// then tiny GEMV. Reads the fp32 master H.
// =====================================================================
__global__ void __launch_bounds__(256) decoder_kernel(const float* __restrict__ Wd,
                                                      const float* __restrict__ bd,
                                                      float* __restrict__ out) {
    const int b = blockIdx.x;
    const int d = threadIdx.x;
    const float* Hb = g_H + (size_t)b * NN * DD;

    float s0 = 0.f, s1 = 0.f, s2 = 0.f, s3 = 0.f;
    #pragma unroll 1
    for (int n = 0; n < NN; n += 4) {
        s0 += Hb[(size_t)(n + 0) * DD + d];
        s1 += Hb[(size_t)(n + 1) * DD + d];
        s2 += Hb[(size_t)(n + 2) * DD + d];
        s3 += Hb[(size_t)(n + 3) * DD + d];
    }
    __shared__ float mean[DD];
    mean[d] = (s0 + s1 + s2 + s3) * (1.0f / (float)NN);
    __syncthreads();

    if (d < OUTD) {
        float o = bd[d];
        #pragma unroll 8
        for (int k = 0; k < DD; ++k)
            o = fmaf(mean[k], Wd[k * OUTD + d], o);
        out[b * OUTD + d] = o;
    }
}

// =====================================================================
// Launch. Inputs (metadata order): 0 bus_type(i32), 1 Yr, 2 Yi,
// 3 features, 4 W_emb, 5 b_emb, 6 Wl, 7 bl, 8 Wd, 9 bd.
// Output: float[8*15].
// =====================================================================
extern "C" void kernel_launch(void* const* d_in, const int* in_sizes, int n_in,
                              void* d_out, int out_size) {
    const int*   bus_type = (const int*)  d_in[0];
    const float* Yr       = (const float*)d_in[1];
    const float* Yi       = (const float*)d_in[2];
    const float* features = (const float*)d_in[3];
    const float* W_emb    = (const float*)d_in[4];
    const float* b_emb    = (const float*)d_in[5];
    const float* Wl       = (const float*)d_in[6];
    const float* bl       = (const float*)d_in[7];
    const float* Wd       = (const float*)d_in[8];
    const float* bd       = (const float*)d_in[9];
    float* out = (float*)d_out;

    adj_kernel<<<TOTROWS / 8, 256>>>(Yr, Yi);
    emb_kernel<<<TOTROWS, 256>>>(bus_type, features, W_emb, b_emb);
    wlt_kernel<<<DD, DD>>>(Wl);

    for (int k = 0; k < KSTEPS; ++k) {
        spmm_kernel<<<TOTROWS / 8, 256>>>();
        update_kernel<<<dim3(TOTROWS / 128, 2), 256>>>(bl);
    }

    decoder_kernel<<<BB, 256>>>(Wd, bd, out);
}